// round 6
// baseline (speedup 1.0000x reference)
#include <cuda_runtime.h>
#include <math.h>
#include <cstdint>

#define SEQ   1024
#define BATCH 128
#define EMB   512
#define HID   512
#define ZDIM  2048               // 4*HID
#define NBH   (BATCH * HID)      // 65536
#define NREC  64                 // recurrent CTAs (32 j-tiles x 2 row-tiles)
#define NPROD 84                 // xz-producer CTAs
#define NTILE (SEQ * 16)         // xz tiles: 1024 timesteps x 16 n-tiles

// Scratch (allocation-free rule: __device__ globals)
__device__ float    g_xz[(size_t)SEQ * BATCH * ZDIM];   // 1 GiB: x@Wx + b
__device__ unsigned g_count;                            // barrier arrivals
__device__ unsigned g_phase;                            // barrier phase
__device__ unsigned g_ready[SEQ];                       // xz tiles done per t

// ---------------------------------------------------------------------------
// helpers
// ---------------------------------------------------------------------------
__device__ __forceinline__ unsigned tf32cvt(float x) {
    unsigned u;
    asm("cvt.rna.tf32.f32 %0, %1;" : "=r"(u) : "f"(x));
    return u;
}

__device__ __forceinline__ void mma_tf32(float* c, const unsigned* a, const unsigned* b) {
    asm volatile(
        "mma.sync.aligned.m16n8k8.row.col.f32.tf32.tf32.f32 "
        "{%0,%1,%2,%3}, {%4,%5,%6,%7}, {%8,%9}, {%0,%1,%2,%3};\n"
        : "+f"(c[0]), "+f"(c[1]), "+f"(c[2]), "+f"(c[3])
        : "r"(a[0]), "r"(a[1]), "r"(a[2]), "r"(a[3]), "r"(b[0]), "r"(b[1]));
}

__device__ __forceinline__ float tanh_ap(float x) {
    float y;
    asm("tanh.approx.f32 %0, %1;" : "=f"(y) : "f"(x));
    return y;
}
__device__ __forceinline__ float sigm_ap(float x) {
    return fmaf(tanh_ap(0.5f * x), 0.5f, 0.5f);
}

// ---------------------------------------------------------------------------
// reset (graph node 1): barrier + ready flags -> deterministic replays
// ---------------------------------------------------------------------------
__global__ void reset_k() {
    int i = threadIdx.x;
    if (i < SEQ) g_ready[i] = 0;
    if (i == 0) { g_count = 0; g_phase = 0; }
}

// ---------------------------------------------------------------------------
// Dynamic smem layout (word offsets), recurrent-CTA view:
//   Bs  [512][72]  : Wh slice, gate-gathered (cached all steps)   147456 B
//   As0 [64][132]  : h chunk, k lo-half of pass                    33792 B
//   As1 [64][132]  : h chunk, k hi-half of pass                    33792 B
//   Zs  [64][65]   : z exchange / K-group reduction                16640 B
// Producer-CTA view (overlay at word 0): Asp[128][17] | Bsp[16][136]
// ---------------------------------------------------------------------------
#define BS_STR  72
#define AS_STR  132
#define SM_AS0  (512 * BS_STR)
#define SM_AS1  (SM_AS0 + 64 * AS_STR)
#define SM_ZS   (SM_AS1 + 64 * AS_STR)
#define SMEM_WORDS (SM_ZS + 64 * 65)
#define SMEM_BYTES (SMEM_WORDS * 4)          // 231680 <= 232448 max

// ---------------------------------------------------------------------------
// Producer role: compute g_xz tiles (128 rows = one timestep, 128 cols),
// publish g_ready[t]. Runs on threads 0..255 only (verified R3/R5 body).
// ---------------------------------------------------------------------------
__device__ void xz_producer(const float* __restrict__ X,
                            const float* __restrict__ W,
                            const float* __restrict__ bias,
                            unsigned* smw, int pid) {
    unsigned (*As)[17]  = (unsigned(*)[17])smw;
    unsigned (*Bs)[136] = (unsigned(*)[136])(smw + 128 * 17);

    const int tid  = threadIdx.x;
    const int lane = tid & 31;
    const int w    = tid >> 5;
    const int wm = (w & 1) * 64;
    const int wn = (w >> 1) * 32;
    const int gid = lane >> 2;
    const int tig = lane & 3;

    for (int idx = pid; idx < NTILE; idx += NPROD) {
        const int t  = idx >> 4;
        const int bn = idx & 15;

        float acc[4][4][4];
        #pragma unroll
        for (int mt = 0; mt < 4; mt++)
            #pragma unroll
            for (int nt = 0; nt < 4; nt++)
                #pragma unroll
                for (int r = 0; r < 4; r++) acc[mt][nt][r] = 0.0f;

        const float* Ag = X + (size_t)t * 128 * EMB;
        const float* Bg = W + (size_t)bn * 128;

        for (int k0 = 0; k0 < EMB; k0 += 16) {
            #pragma unroll
            for (int i = 0; i < 2; i++) {
                int id2 = tid + i * 256;
                int r = id2 >> 2, c4 = id2 & 3;
                float4 v = *(const float4*)(Ag + (size_t)r * EMB + k0 + c4 * 4);
                As[r][c4 * 4 + 0] = tf32cvt(v.x);
                As[r][c4 * 4 + 1] = tf32cvt(v.y);
                As[r][c4 * 4 + 2] = tf32cvt(v.z);
                As[r][c4 * 4 + 3] = tf32cvt(v.w);
            }
            #pragma unroll
            for (int i = 0; i < 2; i++) {
                int id2 = tid + i * 256;
                int r = id2 >> 5, c4 = id2 & 31;
                float4 v = *(const float4*)(Bg + (size_t)(k0 + r) * ZDIM + c4 * 4);
                Bs[r][c4 * 4 + 0] = tf32cvt(v.x);
                Bs[r][c4 * 4 + 1] = tf32cvt(v.y);
                Bs[r][c4 * 4 + 2] = tf32cvt(v.z);
                Bs[r][c4 * 4 + 3] = tf32cvt(v.w);
            }
            __syncthreads();

            #pragma unroll
            for (int kk = 0; kk < 16; kk += 8) {
                unsigned a[4][4], b[4][2];
                #pragma unroll
                for (int mt = 0; mt < 4; mt++) {
                    int mr = wm + mt * 16;
                    a[mt][0] = As[mr + gid][kk + tig];
                    a[mt][1] = As[mr + gid + 8][kk + tig];
                    a[mt][2] = As[mr + gid][kk + tig + 4];
                    a[mt][3] = As[mr + gid + 8][kk + tig + 4];
                }
                #pragma unroll
                for (int nt = 0; nt < 4; nt++) {
                    int nc = wn + nt * 8;
                    b[nt][0] = Bs[kk + tig][nc + gid];
                    b[nt][1] = Bs[kk + tig + 4][nc + gid];
                }
                #pragma unroll
                for (int mt = 0; mt < 4; mt++)
                    #pragma unroll
                    for (int nt = 0; nt < 4; nt++)
                        mma_tf32(acc[mt][nt], a[mt], b[nt]);
            }
            __syncthreads();
        }

        #pragma unroll
        for (int mt = 0; mt < 4; mt++) {
            #pragma unroll
            for (int nt = 0; nt < 4; nt++) {
                int grow = t * 128 + wm + mt * 16 + gid;
                int gcol = bn * 128 + wn + nt * 8 + 2 * tig;
                float b0 = bias[gcol], b1 = bias[gcol + 1];
                float* p0 = g_xz + (size_t)grow * ZDIM + gcol;
                p0[0] = acc[mt][nt][0] + b0;
                p0[1] = acc[mt][nt][1] + b1;
                float* p1 = g_xz + (size_t)(grow + 8) * ZDIM + gcol;
                p1[0] = acc[mt][nt][2] + b0;
                p1[1] = acc[mt][nt][3] + b1;
            }
        }

        __threadfence();          // every thread's STGs visible before flag
        __syncthreads();
        if (tid == 0) atomicAdd(&g_ready[t], 1u);
        __syncthreads();
    }
}

// ---------------------------------------------------------------------------
// grid barrier among the NREC recurrent CTAs (all co-resident, 1 wave)
// ---------------------------------------------------------------------------
__device__ __forceinline__ void grid_sync(unsigned target) {
    __threadfence();             // every thread's h-writes visible chip-wide
    __syncthreads();
    if (threadIdx.x == 0) {
        unsigned arrived = atomicAdd(&g_count, 1u);
        if (arrived == NREC - 1) {
            atomicExch(&g_count, 0u);
            atomicAdd(&g_phase, 1u);
        } else {
            while (atomicAdd(&g_phase, 0u) < target) { __nanosleep(32); }
        }
    }
    __syncthreads();
}

// ---------------------------------------------------------------------------
// Persistent kernel: 148 CTAs x 512 threads, one wave.
//   blockIdx.x <  64 : recurrent role (16 warps)
//   blockIdx.x >= 64 : xz-producer role (threads 0..255; rest exit)
//
// Recurrent GEMM per step: z[64 x 64] = h_prev[64 x 512] @ WhSlice[512 x 64].
// 16 warps: group g = w>>2 (4-way K-split), warp wq = w&3 tiles the 64x64
// output with 32x32 tiles. Per 256-k pass, group g covers k-range
// [pass*256 + g*64, +64): groups 0,1 read As0, groups 2,3 read As1.
// Partials reduced into Zs: group 0 stores, groups 1-3 shared atomicAdd.
// Cell state: 2 fp32 regs/thread. xz prefetched to regs before the GEMM.
// ---------------------------------------------------------------------------
__global__ __launch_bounds__(512, 1) void lstm_persist_k(float* __restrict__ out,
                                                         const float* __restrict__ X,
                                                         const float* __restrict__ W,
                                                         const float* __restrict__ bias) {
    extern __shared__ unsigned smw[];
    const int tid = threadIdx.x;

    if (blockIdx.x >= NREC) {
        if (tid < 256) xz_producer(X, W, bias, smw, blockIdx.x - NREC);
        return;
    }

    unsigned (*Bs)[BS_STR]  = (unsigned(*)[BS_STR])smw;
    unsigned (*As0)[AS_STR] = (unsigned(*)[AS_STR])(smw + SM_AS0);
    unsigned (*As1)[AS_STR] = (unsigned(*)[AS_STR])(smw + SM_AS1);
    float    (*Zs)[65]      = (float(*)[65])(smw + SM_ZS);

    const int cb   = blockIdx.x;
    const int j0   = (cb & 31) * 16;      // hidden-col tile
    const int row0 = (cb >> 5) * 64;      // batch-row tile
    const int lane = tid & 31;
    const int w    = tid >> 5;            // 0..15
    const int grp  = w >> 2;              // K-split group 0..3
    const int wq   = w & 3;               // warp within group
    const int wm   = (wq & 1) * 32;
    const int wn   = (wq >> 1) * 32;
    const int gid  = lane >> 2;
    const int tig  = lane & 3;

    // ---- one-time: cache Wh slice (gate-gathered, tf32) in smem ----
    // Bs[k][n], n = gate*16 + jj  ->  Wh[k][gate*512 + j0 + jj]
    const float* Wh = W + (size_t)EMB * ZDIM;
    #pragma unroll 4
    for (int i = 0; i < 16; i++) {
        int idx  = tid + i * 512;            // 8192 float4s
        int k    = idx >> 4;
        int rem  = idx & 15;
        int gate = rem >> 2, jjq = rem & 3;
        float4 v = *(const float4*)(Wh + (size_t)k * ZDIM + gate * 512 + j0 + jjq * 4);
        int n = gate * 16 + jjq * 4;
        Bs[k][n + 0] = tf32cvt(v.x);
        Bs[k][n + 1] = tf32cvt(v.y);
        Bs[k][n + 2] = tf32cvt(v.z);
        Bs[k][n + 3] = tf32cvt(v.w);
    }
    __syncthreads();

    // cell state: 2 items/thread (item = tid + it*512 -> row item>>4, col item&15)
    float c_reg[2] = {0.0f, 0.0f};

    for (int t = 0; t < SEQ; t++) {
        // ---- wait for xz[t] (producer publishes 16 n-tiles per t) ----
        if (tid == 0) {
            while (atomicAdd(&g_ready[t], 0u) < 16u) { __nanosleep(64); }
        }
        __syncthreads();

        // ---- prefetch xz gate pre-activations into registers ----
        float xf[8];
        {
            const float* xz = g_xz + (size_t)t * BATCH * ZDIM;
            #pragma unroll
            for (int it = 0; it < 2; it++) {
                int item = tid + it * 512;
                int b = item >> 4, jj = item & 15;
                const float* p = xz + (size_t)(row0 + b) * ZDIM + j0 + jj;
                xf[it * 4 + 0] = p[0];
                xf[it * 4 + 1] = p[512];
                xf[it * 4 + 2] = p[1024];
                xf[it * 4 + 3] = p[1536];
            }
        }

        if (t > 0) {
            const float* hp = out + (size_t)(t - 1) * NBH;
            float acc[2][4][4];
            #pragma unroll
            for (int mt = 0; mt < 2; mt++)
                #pragma unroll
                for (int nt = 0; nt < 4; nt++)
                    #pragma unroll
                    for (int r = 0; r < 4; r++) acc[mt][nt][r] = 0.0f;

            unsigned (*A)[AS_STR] = (grp & 2) ? As1 : As0;
            const int ka = (grp & 1) * 64;         // k-offset within A buffer

            #pragma unroll 1
            for (int p2 = 0; p2 < 2; p2++) {
                // load h rows [row0,row0+64) x k [p2*256, +256):
                // first 128 k -> As0, next 128 k -> As1
                #pragma unroll
                for (int i = 0; i < 8; i++) {
                    int idx = tid + i * 512;          // 4096 float4s
                    int r = idx >> 6, c4 = idx & 63;
                    float4 v = *(const float4*)(hp + (size_t)(row0 + r) * HID + p2 * 256 + c4 * 4);
                    unsigned* dst = (c4 < 32) ? &As0[r][c4 * 4] : &As1[r][(c4 - 32) * 4];
                    *(uint4*)dst = make_uint4(tf32cvt(v.x), tf32cvt(v.y),
                                              tf32cvt(v.z), tf32cvt(v.w));
                }
                __syncthreads();

                const int kb = p2 * 256 + grp * 64;   // B k-offset for this group
                #pragma unroll
                for (int kk = 0; kk < 64; kk += 8) {
                    unsigned a[2][4], b[4][2];
                    #pragma unroll
                    for (int mt = 0; mt < 2; mt++) {
                        int mr = wm + mt * 16;
                        a[mt][0] = A[mr + gid][ka + kk + tig];
                        a[mt][1] = A[mr + gid + 8][ka + kk + tig];
                        a[mt][2] = A[mr + gid][ka + kk + tig + 4];
                        a[mt][3] = A[mr + gid + 8][ka + kk + tig + 4];
                    }
                    #pragma unroll
                    for (int nt = 0; nt < 4; nt++) {
                        int nc = wn + nt * 8;
                        b[nt][0] = Bs[kb + kk + tig][nc + gid];
                        b[nt][1] = Bs[kb + kk + tig + 4][nc + gid];
                    }
                    #pragma unroll
                    for (int mt = 0; mt < 2; mt++)
                        #pragma unroll
                        for (int nt = 0; nt < 4; nt++)
                            mma_tf32(acc[mt][nt], a[mt], b[nt]);
                }
                __syncthreads();
            }

            // ---- reduce the 4 K-groups into Zs ----
            if (grp == 0) {
                #pragma unroll
                for (int mt = 0; mt < 2; mt++)
                    #pragma unroll
                    for (int nt = 0; nt < 4; nt++) {
                        int rr  = wm + mt * 16 + gid;
                        int col = wn + nt * 8 + 2 * tig;
                        Zs[rr][col]         = acc[mt][nt][0];
                        Zs[rr][col + 1]     = acc[mt][nt][1];
                        Zs[rr + 8][col]     = acc[mt][nt][2];
                        Zs[rr + 8][col + 1] = acc[mt][nt][3];
                    }
            }
            __syncthreads();
            if (grp != 0) {
                #pragma unroll
                for (int mt = 0; mt < 2; mt++)
                    #pragma unroll
                    for (int nt = 0; nt < 4; nt++) {
                        int rr  = wm + mt * 16 + gid;
                        int col = wn + nt * 8 + 2 * tig;
                        atomicAdd(&Zs[rr][col],         acc[mt][nt][0]);
                        atomicAdd(&Zs[rr][col + 1],     acc[mt][nt][1]);
                        atomicAdd(&Zs[rr + 8][col],     acc[mt][nt][2]);
                        atomicAdd(&Zs[rr + 8][col + 1], acc[mt][nt][3]);
                    }
            }
            __syncthreads();
        }

        // ---- gates + state update: 2 items per thread ----
        float* hout = out + (size_t)t * NBH;
        #pragma unroll
        for (int it = 0; it < 2; it++) {
            int item = tid + it * 512;
            int b = item >> 4, jj = item & 15;
            float zr_i = (t > 0) ? Zs[b][jj]      : 0.0f;
            float zr_f = (t > 0) ? Zs[b][16 + jj] : 0.0f;
            float zr_g = (t > 0) ? Zs[b][32 + jj] : 0.0f;
            float zr_o = (t > 0) ? Zs[b][48 + jj] : 0.0f;
            float ig = sigm_ap(zr_i + xf[it * 4 + 0]);
            float fg = sigm_ap(zr_f + xf[it * 4 + 1]);
            float gg = tanh_ap(zr_g + xf[it * 4 + 2]);
            float og = sigm_ap(zr_o + xf[it * 4 + 3]);
            float cn = fg * c_reg[it] + ig * gg;
            c_reg[it] = cn;
            hout[(size_t)(row0 + b) * HID + j0 + jj] = og * tanh_ap(cn);
        }

        grid_sync((unsigned)(t + 1));
    }

    // ---- epilogue: append hT and cT ----
    {
        const float* hlast = out + (size_t)(SEQ - 1) * NBH;
        float* hT = out + (size_t)SEQ * NBH;
        float* cT = hT + NBH;
        #pragma unroll
        for (int it = 0; it < 2; it++) {
            int item = tid + it * 512;
            int b = item >> 4, jj = item & 15;
            size_t ci = (size_t)(row0 + b) * HID + j0 + jj;
            hT[ci] = hlast[ci];
            cT[ci] = c_reg[it];
        }
    }
}

// ---------------------------------------------------------------------------
extern "C" void kernel_launch(void* const* d_in, const int* in_sizes, int n_in,
                              void* d_out, int out_size) {
    const float* x    = (const float*)d_in[0];
    const float* W    = (const float*)d_in[1];
    const float* bias = (const float*)d_in[2];
    float* out = (float*)d_out;

    cudaFuncSetAttribute(lstm_persist_k,
                         cudaFuncAttributeMaxDynamicSharedMemorySize, SMEM_BYTES);

    reset_k<<<1, 1024>>>();
    lstm_persist_k<<<NREC + NPROD, 512, SMEM_BYTES>>>(out, x, W, bias);
}